// round 16
// baseline (speedup 1.0000x reference)
#include <cuda_runtime.h>
#include <cuda_bf16.h>

#define FDIM 64
#define NMAX 50176

// Scratch (allocation-free rule: __device__ globals)
__device__ __align__(16) float g_u[NMAX * FDIM];
__device__ __align__(16) float g_v[NMAX * FDIM];
__device__ __align__(16) __nv_bfloat16 g_ub[NMAX * FDIM];   // bf16 copy of g_u
__device__ __align__(16) __nv_bfloat16 g_vb[NMAX * FDIM];   // bf16 copy of g_v
__device__ __align__(16) float g_hs[NMAX * FDIM];   // r_out[n] * (x@Ws2d + b)
__device__ __align__(16) float g_hd[NMAX * FDIM];   // r_in[n]  * (x@Wd2s + b)
__device__ __align__(16) float g_min[NMAX * FDIM];
__device__ __align__(16) float g_mout[NMAX * FDIM];
__device__ __align__(16) float g_ideg[NMAX];
__device__ __align__(16) float g_odeg[NMAX];

__device__ __forceinline__ void red4(float* p, float a, float b, float c, float d) {
    asm volatile("red.global.add.v4.f32 [%0], {%1, %2, %3, %4};"
                 :: "l"(__cvta_generic_to_global(p)), "f"(a), "f"(b), "f"(c), "f"(d)
                 : "memory");
}

// ---------------------------------------------------------------- zero degree arrays (tiny)
__global__ void k_zero(int N) {
    int i = blockIdx.x * blockDim.x + threadIdx.x;
    if (i < N) { g_ideg[i] = 0.f; g_odeg[i] = 0.f; }
}

// ---------------------------------------------------------------- degrees (pure atomics)
__global__ void k_deg(const float* __restrict__ counts, const int* __restrict__ src,
                      const int* __restrict__ dst, int E) {
    int i = blockIdx.x * blockDim.x + threadIdx.x;
    if (i < E) {
        float c = __ldg(&counts[i]);
        atomicAdd(&g_ideg[__ldg(&dst[i])], c);
        atomicAdd(&g_odeg[__ldg(&src[i])], c);
    }
}

// ---------------------------------------------------------------- fused node GEMMs
// Also zeroes g_min/g_mout (grid-stride prologue, overlapped with GEMM work).
// g_hs = r_out * (x@Ws2d + bs2d) ; g_hd = r_in * (x@Wd2s + bd2s)
// u = x@Wl1[0:64] + bl1 ; v = x@Wl1[64:128]  (+ bf16 copies)  (runs AFTER k_deg)
__global__ __launch_bounds__(256) void k_node_pre(
    const float* __restrict__ x,
    const float* __restrict__ Ws2d, const float* __restrict__ bs2d,
    const float* __restrict__ Wd2s, const float* __restrict__ bd2s,
    const float* __restrict__ Wl1,  const float* __restrict__ bl1,
    int N)
{
    extern __shared__ float sm[];
    float* sWs = sm;            // 4096
    float* sWd = sm + 4096;     // 4096
    float* sW1 = sm + 8192;     // 8192 (rows 0..127)
    float* sb  = sm + 16384;    // 192
    float* sx  = sm + 16576;    // 64*65 (padded stride)

    int tx = threadIdx.x, ty = threadIdx.y;
    int tid = ty * 16 + tx;

    // ---- zero m arrays (grid-stride; hidden behind the GEMM below) ----
    {
        int gi = blockIdx.x * 256 + tid;
        int gstride = gridDim.x * 256;
        int tot4 = N * (FDIM / 4);
        float4 zz = make_float4(0.f, 0.f, 0.f, 0.f);
        for (int idx = gi; idx < tot4; idx += gstride) {
            reinterpret_cast<float4*>(g_min)[idx] = zz;
            reinterpret_cast<float4*>(g_mout)[idx] = zz;
        }
    }

    for (int i = tid; i < 4096; i += 256) { sWs[i] = Ws2d[i]; sWd[i] = Wd2s[i]; }
    for (int i = tid; i < 8192; i += 256) { sW1[i] = Wl1[i]; }
    if (tid < 64) { sb[tid] = bs2d[tid]; sb[64 + tid] = bd2s[tid]; sb[128 + tid] = bl1[tid]; }

    int nbase = blockIdx.x * 64;
    for (int i = tid; i < 64 * FDIM; i += 256) {
        int r = i >> 6, c = i & 63;
        int n = nbase + r;
        sx[r * 65 + c] = (n < N) ? x[n * FDIM + c] : 0.f;
    }
    __syncthreads();

    int j0 = 4 * tx;
    float4 ahs[4], ahd[4], au[4], av[4];
#pragma unroll
    for (int r = 0; r < 4; r++) {
        ahs[r] = make_float4(0.f, 0.f, 0.f, 0.f);
        ahd[r] = ahs[r]; au[r] = ahs[r]; av[r] = ahs[r];
    }

#pragma unroll 2
    for (int k = 0; k < FDIM; k++) {
        float4 ws = *reinterpret_cast<const float4*>(&sWs[k * 64 + j0]);
        float4 wd = *reinterpret_cast<const float4*>(&sWd[k * 64 + j0]);
        float4 wa = *reinterpret_cast<const float4*>(&sW1[k * 64 + j0]);
        float4 wb = *reinterpret_cast<const float4*>(&sW1[(k + 64) * 64 + j0]);
#pragma unroll
        for (int r = 0; r < 4; r++) {
            float xv = sx[(ty + 16 * r) * 65 + k];
            ahs[r].x += xv * ws.x; ahs[r].y += xv * ws.y; ahs[r].z += xv * ws.z; ahs[r].w += xv * ws.w;
            ahd[r].x += xv * wd.x; ahd[r].y += xv * wd.y; ahd[r].z += xv * wd.z; ahd[r].w += xv * wd.w;
            au[r].x  += xv * wa.x; au[r].y  += xv * wa.y; au[r].z  += xv * wa.z; au[r].w  += xv * wa.w;
            av[r].x  += xv * wb.x; av[r].y  += xv * wb.y; av[r].z  += xv * wb.z; av[r].w  += xv * wb.w;
        }
    }

#pragma unroll
    for (int r = 0; r < 4; r++) {
        int n = nbase + ty + 16 * r;
        if (n < N) {
            float ro = rsqrtf(fmaxf(__ldg(&g_odeg[n]), 1.f));
            float ri = rsqrtf(fmaxf(__ldg(&g_ideg[n]), 1.f));
            ahs[r].x = ro * (ahs[r].x + sb[j0]);       ahs[r].y = ro * (ahs[r].y + sb[j0 + 1]);
            ahs[r].z = ro * (ahs[r].z + sb[j0 + 2]);   ahs[r].w = ro * (ahs[r].w + sb[j0 + 3]);
            ahd[r].x = ri * (ahd[r].x + sb[64 + j0]);  ahd[r].y = ri * (ahd[r].y + sb[64 + j0 + 1]);
            ahd[r].z = ri * (ahd[r].z + sb[64 + j0 + 2]); ahd[r].w = ri * (ahd[r].w + sb[64 + j0 + 3]);
            au[r].x  += sb[128 + j0]; au[r].y  += sb[128 + j0 + 1]; au[r].z  += sb[128 + j0 + 2]; au[r].w  += sb[128 + j0 + 3];
            *reinterpret_cast<float4*>(&g_hs[n * FDIM + j0]) = ahs[r];
            *reinterpret_cast<float4*>(&g_hd[n * FDIM + j0]) = ahd[r];
            *reinterpret_cast<float4*>(&g_u[n * FDIM + j0])  = au[r];
            *reinterpret_cast<float4*>(&g_v[n * FDIM + j0])  = av[r];

            // bf16 copies for the edge fast path (quad tx of row n)
            __nv_bfloat162 u0 = __float22bfloat162_rn(make_float2(au[r].x, au[r].y));
            __nv_bfloat162 u1 = __float22bfloat162_rn(make_float2(au[r].z, au[r].w));
            __nv_bfloat162 v0 = __float22bfloat162_rn(make_float2(av[r].x, av[r].y));
            __nv_bfloat162 v1 = __float22bfloat162_rn(make_float2(av[r].z, av[r].w));
            uint2 pu, pv;
            pu.x = *reinterpret_cast<unsigned int*>(&u0);
            pu.y = *reinterpret_cast<unsigned int*>(&u1);
            pv.x = *reinterpret_cast<unsigned int*>(&v0);
            pv.y = *reinterpret_cast<unsigned int*>(&v1);
            reinterpret_cast<uint2*>(g_ub)[n * 16 + tx] = pu;
            reinterpret_cast<uint2*>(g_vb)[n * 16 + tx] = pv;
        }
    }
}

// ---------------------------------------------------------------- edge kernel
// 4 edges per warp. Phase 1: bf16 u/v gathers (half sector traffic) + z.
// Near-threshold edges (|z+b| < TAU) recompute z from the fp32 rows with the
// identical reduction order -> keep decisions bit-identical to the fp32 kernel.
// Phase 2: keep-predicated fp32 h gathers + REDs.
#define TAU 0.08f
__global__ __launch_bounds__(256) void k_edge(
    const float* __restrict__ counts, const int* __restrict__ src,
    const int* __restrict__ dst, const float* __restrict__ Wl2,
    const float* __restrict__ bl2, int E)
{
    int lane = threadIdx.x & 31;
    int wid = (blockIdx.x * blockDim.x + threadIdx.x) >> 5;
    int e0 = wid * 4;
    if (e0 >= E) return;

    int half = lane >> 4;
    int q = lane & 15;

    float4 w2 = __ldg(reinterpret_cast<const float4*>(Wl2) + q);
    float blv = __ldg(bl2);

    int s[4], d[4], n[4];
    float c[4];
#pragma unroll
    for (int i = 0; i < 4; i++) {
        int e = (e0 + i < E) ? (e0 + i) : (E - 1);
        s[i] = __ldg(&src[e]);
        d[i] = __ldg(&dst[e]);
        c[i] = __ldg(&counts[e]);
        n[i] = half ? d[i] : s[i];
    }

    const uint2*  uvb16 = reinterpret_cast<const uint2*>(half ? g_vb : g_ub);
    const float4* uvb32 = reinterpret_cast<const float4*>(half ? g_v : g_u);
    const float4* hb    = reinterpret_cast<const float4*>(half ? g_hd : g_hs);

    // ---- phase 1: batched bf16 gathers (8 independent LDG.64) ----
    uint2 raw[4];
#pragma unroll
    for (int i = 0; i < 4; i++)
        raw[i] = __ldg(uvb16 + (size_t)n[i] * 16 + q);

    float z[4];
#pragma unroll
    for (int i = 0; i < 4; i++) {
        __nv_bfloat162 p0 = *reinterpret_cast<__nv_bfloat162*>(&raw[i].x);
        __nv_bfloat162 p1 = *reinterpret_cast<__nv_bfloat162*>(&raw[i].y);
        float2 f0 = __bfloat1622float2(p0);
        float2 f1 = __bfloat1622float2(p1);
        float ax = f0.x, ay = f0.y, az = f1.x, aw = f1.y;
        float bx = __shfl_xor_sync(0xffffffffu, ax, 16);
        float by = __shfl_xor_sync(0xffffffffu, ay, 16);
        float bz = __shfl_xor_sync(0xffffffffu, az, 16);
        float bw = __shfl_xor_sync(0xffffffffu, aw, 16);
        z[i] = fmaxf(ax + bx, 0.f) * w2.x + fmaxf(ay + by, 0.f) * w2.y
             + fmaxf(az + bz, 0.f) * w2.z + fmaxf(aw + bw, 0.f) * w2.w;
    }
#pragma unroll
    for (int off = 8; off; off >>= 1) {
#pragma unroll
        for (int i = 0; i < 4; i++) z[i] += __shfl_xor_sync(0xffffffffu, z[i], off);
    }

    // ---- fp32 fallback for near-threshold edges (warp-uniform branches) ----
#pragma unroll
    for (int i = 0; i < 4; i++) {
        if (fabsf(z[i] + blv) < TAU) {
            float4 a = __ldg(uvb32 + (size_t)n[i] * 16 + q);
            float bx = __shfl_xor_sync(0xffffffffu, a.x, 16);
            float by = __shfl_xor_sync(0xffffffffu, a.y, 16);
            float bz = __shfl_xor_sync(0xffffffffu, a.z, 16);
            float bw = __shfl_xor_sync(0xffffffffu, a.w, 16);
            float zz = fmaxf(a.x + bx, 0.f) * w2.x + fmaxf(a.y + by, 0.f) * w2.y
                     + fmaxf(a.z + bz, 0.f) * w2.z + fmaxf(a.w + bw, 0.f) * w2.w;
#pragma unroll
            for (int off = 8; off; off >>= 1) zz += __shfl_xor_sync(0xffffffffu, zz, off);
            z[i] = zz;
        }
    }

    // ---- phase 2: keep-predicated h gathers + scatters ----
    bool keep[4];
    float4 h[4];
#pragma unroll
    for (int i = 0; i < 4; i++) {
        keep[i] = (z[i] + blv >= 0.f) && (e0 + i < E);   // sigmoid(z) >= 0.5 <=> z >= 0
        h[i] = make_float4(0.f, 0.f, 0.f, 0.f);
        if (keep[i]) h[i] = __ldg(hb + (size_t)n[i] * 16 + q);
    }
#pragma unroll
    for (int i = 0; i < 4; i++) {
        if (keep[i]) {
            float* tgt = half ? &g_mout[s[i] * FDIM + 4 * q] : &g_min[d[i] * FDIM + 4 * q];
            red4(tgt, c[i] * h[i].x, c[i] * h[i].y, c[i] * h[i].z, c[i] * h[i].w);
        }
    }
}

// ---------------------------------------------------------------- gate + blend + residual
// Block-tiled GEMM: 64 nodes/block, blockDim (16,16), tx = j-quad, ty+16r = node.
// m_in = r_in[n]*acc_in, m_out = r_out[n]*acc_out (scaled at smem-load time).
__global__ __launch_bounds__(256) void k_gate(
    const float* __restrict__ x,
    const float* __restrict__ Wg1, const float* __restrict__ bg1,
    const float* __restrict__ Wg2, const float* __restrict__ bg2,
    float* __restrict__ out, int N)
{
    extern __shared__ float gsm[];
    float* sW  = gsm;           // 8192  (Wg1: 128 x 64)
    float* sb1 = gsm + 8192;    // 64
    float* sw2 = gsm + 8256;    // 64
    float* srs = gsm + 8320;    // 128  (r_in, r_out per local node)
    float* sx  = gsm + 8448;    // 64 * 132 (m_in | m_out, scaled; padded stride)

    int tx = threadIdx.x, ty = threadIdx.y;
    int tid = ty * 16 + tx;
    int nbase = blockIdx.x * 64;

    for (int i = tid; i < 8192; i += 256) sW[i] = Wg1[i];
    if (tid < 64) { sb1[tid] = bg1[tid]; sw2[tid] = Wg2[tid]; }
    if (tid < 64) {
        int n = nbase + tid;
        float ri = 1.f, ro = 1.f;
        if (n < N) {
            ri = rsqrtf(fmaxf(g_ideg[n], 1.f));
            ro = rsqrtf(fmaxf(g_odeg[n], 1.f));
        }
        srs[2 * tid] = ri;
        srs[2 * tid + 1] = ro;
    }
    __syncthreads();

    for (int i = tid; i < 64 * 64; i += 256) {
        int r = i >> 6, c = i & 63;
        int n = nbase + r;
        float mi = 0.f, mo = 0.f;
        if (n < N) {
            mi = srs[2 * r] * g_min[n * FDIM + c];
            mo = srs[2 * r + 1] * g_mout[n * FDIM + c];
        }
        sx[r * 132 + c] = mi;
        sx[r * 132 + 64 + c] = mo;
    }
    __syncthreads();

    int j0 = 4 * tx;
    float4 acc[4];
#pragma unroll
    for (int r = 0; r < 4; r++)
        acc[r] = make_float4(sb1[j0], sb1[j0 + 1], sb1[j0 + 2], sb1[j0 + 3]);

#pragma unroll 4
    for (int k = 0; k < 128; k++) {
        float4 w = *reinterpret_cast<const float4*>(&sW[k * 64 + j0]);
#pragma unroll
        for (int r = 0; r < 4; r++) {
            float xv = sx[(ty + 16 * r) * 132 + k];
            acc[r].x += xv * w.x; acc[r].y += xv * w.y;
            acc[r].z += xv * w.z; acc[r].w += xv * w.w;
        }
    }

    float w2a = sw2[j0], w2b = sw2[j0 + 1], w2c = sw2[j0 + 2], w2d = sw2[j0 + 3];
    float bg2v = bg2[0];
#pragma unroll
    for (int r = 0; r < 4; r++) {
        float z = fmaxf(acc[r].x, 0.f) * w2a + fmaxf(acc[r].y, 0.f) * w2b
                + fmaxf(acc[r].z, 0.f) * w2c + fmaxf(acc[r].w, 0.f) * w2d;
#pragma unroll
        for (int off = 8; off; off >>= 1) z += __shfl_xor_sync(0xffffffffu, z, off);

        int row = ty + 16 * r;
        int n = nbase + row;
        if (n < N) {
            float gate = 1.f / (1.f + __expf(-(z + bg2v)));
            float ga = 0.5f * gate;        // ALPHA * gate
            float gb = 0.5f - ga;          // (1-ALPHA) * (1-gate)
            float4 mi = *reinterpret_cast<const float4*>(&sx[row * 132 + j0]);
            float4 mo = *reinterpret_cast<const float4*>(&sx[row * 132 + 64 + j0]);
            float4 xr = __ldg(reinterpret_cast<const float4*>(&x[n * FDIM + j0]));
            float4 o;
            o.x = ga * mi.x + gb * mo.x + xr.x;
            o.y = ga * mi.y + gb * mo.y + xr.y;
            o.z = ga * mi.z + gb * mo.z + xr.z;
            o.w = ga * mi.w + gb * mo.w + xr.w;
            *reinterpret_cast<float4*>(&out[n * FDIM + j0]) = o;
        }
    }
}

// ---------------------------------------------------------------- launch
extern "C" void kernel_launch(void* const* d_in, const int* in_sizes, int n_in,
                              void* d_out, int out_size) {
    const float* x      = (const float*)d_in[0];
    const float* counts = (const float*)d_in[1];
    const float* Ws2d   = (const float*)d_in[2];
    const float* bs2d   = (const float*)d_in[3];
    const float* Wd2s   = (const float*)d_in[4];
    const float* bd2s   = (const float*)d_in[5];
    const float* Wl1    = (const float*)d_in[6];
    const float* bl1    = (const float*)d_in[7];
    const float* Wl2    = (const float*)d_in[8];
    const float* bl2    = (const float*)d_in[9];
    const float* Wg1    = (const float*)d_in[10];
    const float* bg1    = (const float*)d_in[11];
    const float* Wg2    = (const float*)d_in[12];
    const float* bg2    = (const float*)d_in[13];
    const int*   src    = (const int*)d_in[14];
    const int*   dst    = (const int*)d_in[15];
    float* out = (float*)d_out;

    int N = in_sizes[0] / FDIM;
    int E = in_sizes[1];

    // Deterministic every call (no static guards — harness rule).
    cudaFuncSetAttribute(k_node_pre, cudaFuncAttributeMaxDynamicSharedMemorySize, 82944);
    cudaFuncSetAttribute(k_gate, cudaFuncAttributeMaxDynamicSharedMemorySize, 68352);

    k_zero<<<(N + 255) / 256, 256>>>(N);
    k_deg<<<(E + 255) / 256, 256>>>(counts, src, dst, E);

    dim3 bpre(16, 16);
    k_node_pre<<<(N + 63) / 64, bpre, 82944>>>(x, Ws2d, bs2d, Wd2s, bd2s, Wl1, bl1, N);

    // 4 edges per warp, 8 warps per block -> 32 edges per block
    int edge_blocks = (E + 31) / 32;
    k_edge<<<edge_blocks, 256>>>(counts, src, dst, Wl2, bl2, E);

    k_gate<<<(N + 63) / 64, bpre, 68352>>>(x, Wg1, bg1, Wg2, bg2, out, N);
}

// round 17
// speedup vs baseline: 1.2579x; 1.2579x over previous
#include <cuda_runtime.h>

#define FDIM 64
#define NMAX 50176

// Scratch (allocation-free rule: __device__ globals)
__device__ __align__(16) float g_u[NMAX * FDIM];
__device__ __align__(16) float g_v[NMAX * FDIM];
__device__ __align__(16) float g_hs[NMAX * FDIM];   // r_out[n] * (x@Ws2d + b)
__device__ __align__(16) float g_hd[NMAX * FDIM];   // r_in[n]  * (x@Wd2s + b)
__device__ __align__(16) float g_min[NMAX * FDIM];
__device__ __align__(16) float g_mout[NMAX * FDIM];
__device__ __align__(16) float g_ideg[NMAX];
__device__ __align__(16) float g_odeg[NMAX];

__device__ __forceinline__ void red4(float* p, float a, float b, float c, float d) {
    asm volatile("red.global.add.v4.f32 [%0], {%1, %2, %3, %4};"
                 :: "l"(__cvta_generic_to_global(p)), "f"(a), "f"(b), "f"(c), "f"(d)
                 : "memory");
}

// ---------------------------------------------------------------- zero degree arrays (tiny)
__global__ void k_zero(int N) {
    int i = blockIdx.x * blockDim.x + threadIdx.x;
    if (i < N) { g_ideg[i] = 0.f; g_odeg[i] = 0.f; }
}

// ---------------------------------------------------------------- degrees (pure atomics)
__global__ void k_deg(const float* __restrict__ counts, const int* __restrict__ src,
                      const int* __restrict__ dst, int E) {
    int i = blockIdx.x * blockDim.x + threadIdx.x;
    if (i < E) {
        float c = __ldg(&counts[i]);
        atomicAdd(&g_ideg[__ldg(&dst[i])], c);
        atomicAdd(&g_odeg[__ldg(&src[i])], c);
    }
}

// ---------------------------------------------------------------- fused node GEMMs (persistent)
// Grid-stride over 64-node tiles; weights loaded into smem ONCE per block.
// Also zeroes g_min/g_mout (grid-stride prologue, overlapped with GEMM work).
// g_hs = r_out * (x@Ws2d + bs2d) ; g_hd = r_in * (x@Wd2s + bd2s)
// u = x@Wl1[0:64] + bl1 ; v = x@Wl1[64:128]     (runs AFTER k_deg)
__global__ __launch_bounds__(256) void k_node_pre(
    const float* __restrict__ x,
    const float* __restrict__ Ws2d, const float* __restrict__ bs2d,
    const float* __restrict__ Wd2s, const float* __restrict__ bd2s,
    const float* __restrict__ Wl1,  const float* __restrict__ bl1,
    int N)
{
    extern __shared__ float sm[];
    float* sWs = sm;            // 4096
    float* sWd = sm + 4096;     // 4096
    float* sW1 = sm + 8192;     // 8192 (rows 0..127)
    float* sb  = sm + 16384;    // 192
    float* sx  = sm + 16576;    // 64*65 (padded stride)

    int tx = threadIdx.x, ty = threadIdx.y;
    int tid = ty * 16 + tx;

    // ---- zero m arrays (grid-stride; hidden behind the GEMM below) ----
    {
        int gi = blockIdx.x * 256 + tid;
        int gstride = gridDim.x * 256;
        int tot4 = N * (FDIM / 4);
        float4 zz = make_float4(0.f, 0.f, 0.f, 0.f);
        for (int idx = gi; idx < tot4; idx += gstride) {
            reinterpret_cast<float4*>(g_min)[idx] = zz;
            reinterpret_cast<float4*>(g_mout)[idx] = zz;
        }
    }

    for (int i = tid; i < 4096; i += 256) { sWs[i] = Ws2d[i]; sWd[i] = Wd2s[i]; }
    for (int i = tid; i < 8192; i += 256) { sW1[i] = Wl1[i]; }
    if (tid < 64) { sb[tid] = bs2d[tid]; sb[64 + tid] = bd2s[tid]; sb[128 + tid] = bl1[tid]; }

    int j0 = 4 * tx;

    for (int nbase = blockIdx.x * 64; nbase < N; nbase += gridDim.x * 64) {
        __syncthreads();   // weights ready (first iter) / prev tile's sx reads done
        for (int i = tid; i < 64 * FDIM; i += 256) {
            int r = i >> 6, c = i & 63;
            int n = nbase + r;
            sx[r * 65 + c] = (n < N) ? x[n * FDIM + c] : 0.f;
        }
        __syncthreads();

        float4 ahs[4], ahd[4], au[4], av[4];
#pragma unroll
        for (int r = 0; r < 4; r++) {
            ahs[r] = make_float4(0.f, 0.f, 0.f, 0.f);
            ahd[r] = ahs[r]; au[r] = ahs[r]; av[r] = ahs[r];
        }

#pragma unroll 2
        for (int k = 0; k < FDIM; k++) {
            float4 ws = *reinterpret_cast<const float4*>(&sWs[k * 64 + j0]);
            float4 wd = *reinterpret_cast<const float4*>(&sWd[k * 64 + j0]);
            float4 wa = *reinterpret_cast<const float4*>(&sW1[k * 64 + j0]);
            float4 wb = *reinterpret_cast<const float4*>(&sW1[(k + 64) * 64 + j0]);
#pragma unroll
            for (int r = 0; r < 4; r++) {
                float xv = sx[(ty + 16 * r) * 65 + k];
                ahs[r].x += xv * ws.x; ahs[r].y += xv * ws.y; ahs[r].z += xv * ws.z; ahs[r].w += xv * ws.w;
                ahd[r].x += xv * wd.x; ahd[r].y += xv * wd.y; ahd[r].z += xv * wd.z; ahd[r].w += xv * wd.w;
                au[r].x  += xv * wa.x; au[r].y  += xv * wa.y; au[r].z  += xv * wa.z; au[r].w  += xv * wa.w;
                av[r].x  += xv * wb.x; av[r].y  += xv * wb.y; av[r].z  += xv * wb.z; av[r].w  += xv * wb.w;
            }
        }

#pragma unroll
        for (int r = 0; r < 4; r++) {
            int n = nbase + ty + 16 * r;
            if (n < N) {
                float ro = rsqrtf(fmaxf(__ldg(&g_odeg[n]), 1.f));
                float ri = rsqrtf(fmaxf(__ldg(&g_ideg[n]), 1.f));
                ahs[r].x = ro * (ahs[r].x + sb[j0]);       ahs[r].y = ro * (ahs[r].y + sb[j0 + 1]);
                ahs[r].z = ro * (ahs[r].z + sb[j0 + 2]);   ahs[r].w = ro * (ahs[r].w + sb[j0 + 3]);
                ahd[r].x = ri * (ahd[r].x + sb[64 + j0]);  ahd[r].y = ri * (ahd[r].y + sb[64 + j0 + 1]);
                ahd[r].z = ri * (ahd[r].z + sb[64 + j0 + 2]); ahd[r].w = ri * (ahd[r].w + sb[64 + j0 + 3]);
                au[r].x  += sb[128 + j0]; au[r].y  += sb[128 + j0 + 1]; au[r].z  += sb[128 + j0 + 2]; au[r].w  += sb[128 + j0 + 3];
                *reinterpret_cast<float4*>(&g_hs[n * FDIM + j0]) = ahs[r];
                *reinterpret_cast<float4*>(&g_hd[n * FDIM + j0]) = ahd[r];
                *reinterpret_cast<float4*>(&g_u[n * FDIM + j0])  = au[r];
                *reinterpret_cast<float4*>(&g_v[n * FDIM + j0])  = av[r];
            }
        }
    }
}

// ---------------------------------------------------------------- edge kernel
// 4 edges per warp. Phase 1: batched u/v gathers + z for all 4 edges.
// Phase 2: keep-predicated h gathers + REDs (warp-uniform predicates).
__global__ __launch_bounds__(256) void k_edge(
    const float* __restrict__ counts, const int* __restrict__ src,
    const int* __restrict__ dst, const float* __restrict__ Wl2,
    const float* __restrict__ bl2, int E)
{
    int lane = threadIdx.x & 31;
    int wid = (blockIdx.x * blockDim.x + threadIdx.x) >> 5;
    int e0 = wid * 4;
    if (e0 >= E) return;

    int half = lane >> 4;
    int q = lane & 15;

    float4 w2 = __ldg(reinterpret_cast<const float4*>(Wl2) + q);
    float blv = __ldg(bl2);

    int s[4], d[4];
    float c[4];
#pragma unroll
    for (int i = 0; i < 4; i++) {
        int e = (e0 + i < E) ? (e0 + i) : (E - 1);
        s[i] = __ldg(&src[e]);
        d[i] = __ldg(&dst[e]);
        c[i] = __ldg(&counts[e]);
    }

    const float4* uvb = reinterpret_cast<const float4*>(half ? g_v : g_u);
    const float4* hb  = reinterpret_cast<const float4*>(half ? g_hd : g_hs);

    // ---- phase 1: batched u/v gathers (8 independent row-LDG.128) ----
    float4 a[4];
#pragma unroll
    for (int i = 0; i < 4; i++) {
        int n = half ? d[i] : s[i];
        a[i] = __ldg(uvb + (size_t)n * 16 + q);
    }

    float z[4];
#pragma unroll
    for (int i = 0; i < 4; i++) {
        float bx = __shfl_xor_sync(0xffffffffu, a[i].x, 16);
        float by = __shfl_xor_sync(0xffffffffu, a[i].y, 16);
        float bz = __shfl_xor_sync(0xffffffffu, a[i].z, 16);
        float bw = __shfl_xor_sync(0xffffffffu, a[i].w, 16);
        z[i] = fmaxf(a[i].x + bx, 0.f) * w2.x + fmaxf(a[i].y + by, 0.f) * w2.y
             + fmaxf(a[i].z + bz, 0.f) * w2.z + fmaxf(a[i].w + bw, 0.f) * w2.w;
    }
#pragma unroll
    for (int off = 8; off; off >>= 1) {
#pragma unroll
        for (int i = 0; i < 4; i++) z[i] += __shfl_xor_sync(0xffffffffu, z[i], off);
    }

    // ---- phase 2: keep-predicated h gathers + scatters ----
    bool keep[4];
    float4 h[4];
#pragma unroll
    for (int i = 0; i < 4; i++) {
        keep[i] = (z[i] + blv >= 0.f) && (e0 + i < E);   // sigmoid(z) >= 0.5 <=> z >= 0
        h[i] = make_float4(0.f, 0.f, 0.f, 0.f);
        if (keep[i]) {
            int n = half ? d[i] : s[i];
            h[i] = __ldg(hb + (size_t)n * 16 + q);
        }
    }
#pragma unroll
    for (int i = 0; i < 4; i++) {
        if (keep[i]) {
            float* tgt = half ? &g_mout[s[i] * FDIM + 4 * q] : &g_min[d[i] * FDIM + 4 * q];
            red4(tgt, c[i] * h[i].x, c[i] * h[i].y, c[i] * h[i].z, c[i] * h[i].w);
        }
    }
}

// ---------------------------------------------------------------- gate + blend + residual (persistent)
// Grid-stride over 64-node tiles; Wg1 loaded into smem ONCE per block.
// m_in = r_in[n]*acc_in, m_out = r_out[n]*acc_out (scaled at smem-load time).
__global__ __launch_bounds__(256) void k_gate(
    const float* __restrict__ x,
    const float* __restrict__ Wg1, const float* __restrict__ bg1,
    const float* __restrict__ Wg2, const float* __restrict__ bg2,
    float* __restrict__ out, int N)
{
    extern __shared__ float gsm[];
    float* sW  = gsm;           // 8192  (Wg1: 128 x 64)
    float* sb1 = gsm + 8192;    // 64
    float* sw2 = gsm + 8256;    // 64
    float* srs = gsm + 8320;    // 128  (r_in, r_out per local node)
    float* sx  = gsm + 8448;    // 64 * 132 (m_in | m_out, scaled; padded stride)

    int tx = threadIdx.x, ty = threadIdx.y;
    int tid = ty * 16 + tx;

    for (int i = tid; i < 8192; i += 256) sW[i] = Wg1[i];
    if (tid < 64) { sb1[tid] = bg1[tid]; sw2[tid] = Wg2[tid]; }

    int j0 = 4 * tx;
    float w2a_ready = 0.f;  // filled after first sync
    (void)w2a_ready;
    float bg2v = __ldg(bg2);

    for (int nbase = blockIdx.x * 64; nbase < N; nbase += gridDim.x * 64) {
        __syncthreads();   // weights ready (first iter) / prev tile's smem reads done
        if (tid < 64) {
            int n = nbase + tid;
            float ri = 1.f, ro = 1.f;
            if (n < N) {
                ri = rsqrtf(fmaxf(g_ideg[n], 1.f));
                ro = rsqrtf(fmaxf(g_odeg[n], 1.f));
            }
            srs[2 * tid] = ri;
            srs[2 * tid + 1] = ro;
        }
        __syncthreads();

        for (int i = tid; i < 64 * 64; i += 256) {
            int r = i >> 6, c = i & 63;
            int n = nbase + r;
            float mi = 0.f, mo = 0.f;
            if (n < N) {
                mi = srs[2 * r] * g_min[n * FDIM + c];
                mo = srs[2 * r + 1] * g_mout[n * FDIM + c];
            }
            sx[r * 132 + c] = mi;
            sx[r * 132 + 64 + c] = mo;
        }
        __syncthreads();

        float4 acc[4];
#pragma unroll
        for (int r = 0; r < 4; r++)
            acc[r] = make_float4(sb1[j0], sb1[j0 + 1], sb1[j0 + 2], sb1[j0 + 3]);

#pragma unroll 4
        for (int k = 0; k < 128; k++) {
            float4 w = *reinterpret_cast<const float4*>(&sW[k * 64 + j0]);
#pragma unroll
            for (int r = 0; r < 4; r++) {
                float xv = sx[(ty + 16 * r) * 132 + k];
                acc[r].x += xv * w.x; acc[r].y += xv * w.y;
                acc[r].z += xv * w.z; acc[r].w += xv * w.w;
            }
        }

        float w2a = sw2[j0], w2b = sw2[j0 + 1], w2c = sw2[j0 + 2], w2d = sw2[j0 + 3];
#pragma unroll
        for (int r = 0; r < 4; r++) {
            float z = fmaxf(acc[r].x, 0.f) * w2a + fmaxf(acc[r].y, 0.f) * w2b
                    + fmaxf(acc[r].z, 0.f) * w2c + fmaxf(acc[r].w, 0.f) * w2d;
#pragma unroll
            for (int off = 8; off; off >>= 1) z += __shfl_xor_sync(0xffffffffu, z, off);

            int row = ty + 16 * r;
            int n = nbase + row;
            if (n < N) {
                float gate = 1.f / (1.f + __expf(-(z + bg2v)));
                float ga = 0.5f * gate;        // ALPHA * gate
                float gb = 0.5f - ga;          // (1-ALPHA) * (1-gate)
                float4 mi = *reinterpret_cast<const float4*>(&sx[row * 132 + j0]);
                float4 mo = *reinterpret_cast<const float4*>(&sx[row * 132 + 64 + j0]);
                float4 xr = __ldg(reinterpret_cast<const float4*>(&x[n * FDIM + j0]));
                float4 o;
                o.x = ga * mi.x + gb * mo.x + xr.x;
                o.y = ga * mi.y + gb * mo.y + xr.y;
                o.z = ga * mi.z + gb * mo.z + xr.z;
                o.w = ga * mi.w + gb * mo.w + xr.w;
                *reinterpret_cast<float4*>(&out[n * FDIM + j0]) = o;
            }
        }
    }
}

// ---------------------------------------------------------------- launch
extern "C" void kernel_launch(void* const* d_in, const int* in_sizes, int n_in,
                              void* d_out, int out_size) {
    const float* x      = (const float*)d_in[0];
    const float* counts = (const float*)d_in[1];
    const float* Ws2d   = (const float*)d_in[2];
    const float* bs2d   = (const float*)d_in[3];
    const float* Wd2s   = (const float*)d_in[4];
    const float* bd2s   = (const float*)d_in[5];
    const float* Wl1    = (const float*)d_in[6];
    const float* bl1    = (const float*)d_in[7];
    const float* Wl2    = (const float*)d_in[8];
    const float* bl2    = (const float*)d_in[9];
    const float* Wg1    = (const float*)d_in[10];
    const float* bg1    = (const float*)d_in[11];
    const float* Wg2    = (const float*)d_in[12];
    const float* bg2    = (const float*)d_in[13];
    const int*   src    = (const int*)d_in[14];
    const int*   dst    = (const int*)d_in[15];
    float* out = (float*)d_out;

    int N = in_sizes[0] / FDIM;
    int E = in_sizes[1];

    // Deterministic every call (no static guards — harness rule).
    cudaFuncSetAttribute(k_node_pre, cudaFuncAttributeMaxDynamicSharedMemorySize, 82944);
    cudaFuncSetAttribute(k_gate, cudaFuncAttributeMaxDynamicSharedMemorySize, 68352);

    k_zero<<<(N + 255) / 256, 256>>>(N);
    k_deg<<<(E + 255) / 256, 256>>>(counts, src, dst, E);

    dim3 bpre(16, 16);
    int tiles = (N + 63) / 64;

    // persistent: 2 blocks/SM * 148 SMs (smem-limited)
    int pre_blocks = tiles < 296 ? tiles : 296;
    k_node_pre<<<pre_blocks, bpre, 82944>>>(x, Ws2d, bs2d, Wd2s, bd2s, Wl1, bl1, N);

    // 4 edges per warp, 8 warps per block -> 32 edges per block
    int edge_blocks = (E + 31) / 32;
    k_edge<<<edge_blocks, 256>>>(counts, src, dst, Wl2, bl2, E);

    // persistent: 3 blocks/SM * 148 SMs (smem-limited)
    int gate_blocks = tiles < 444 ? tiles : 444;
    k_gate<<<gate_blocks, bpre, 68352>>>(x, Wg1, bg1, Wg2, bg2, out, N);
}